// round 1
// baseline (speedup 1.0000x reference)
#include <cuda_runtime.h>
#include <math.h>

#define B_  4
#define F_  512
#define T_  2048
#define H_  4
#define HF  128   // F_/H_
#define DR  64    // rotated head dim (2*32)
#define NW  32    // quarter width

// ---------------- scratch (device globals; no allocation allowed) ----------
__device__ float d_Q [B_*T_*F_];
__device__ float d_K [B_*T_*F_];
__device__ float d_V [B_*T_*F_];
__device__ float d_Q1[B_*H_*T_*DR];
__device__ float d_Q2[B_*H_*T_*DR];
__device__ float d_K1[B_*H_*T_*DR];
__device__ float d_K2[B_*H_*T_*DR];
__device__ float d_Vh[B_*H_*T_*HF];
__device__ float d_S1[(size_t)B_*H_*T_*T_];   // also holds A after softmax_combine
__device__ float d_S2[(size_t)B_*H_*T_*T_];
__device__ float d_R [B_*T_*F_];

// ---------------------------------------------------------------------------
// QKV projection: out[b,t,n] = sum_f x[b,f,t] * W[n,f] + bias[n]
// 64x64 tile, BK=16, 256 threads, 4x4 microtile.
// ---------------------------------------------------------------------------
__global__ void qkv_gemm(const float* __restrict__ x, const float* __restrict__ W,
                         const float* __restrict__ bias, int sel)
{
    float* out = (sel == 0) ? d_Q : (sel == 1) ? d_K : d_V;
    const int b  = blockIdx.z;
    const int t0 = blockIdx.x * 64;
    const int n0 = blockIdx.y * 64;

    __shared__ float As[16][68];
    __shared__ float Bs[16][68];

    const int tid = threadIdx.x;
    const int tm4 = (tid & 15) * 4;
    const int tn4 = (tid >> 4) * 4;

    float acc[4][4] = {};

    const float* xb = x + (size_t)b * F_ * T_;

    for (int f0 = 0; f0 < F_; f0 += 16) {
        #pragma unroll
        for (int i = 0; i < 4; i++) {
            int idx = tid + i * 256;
            int kk = idx >> 6, tm = idx & 63;       // A: coalesced along t
            As[kk][tm] = xb[(size_t)(f0 + kk) * T_ + t0 + tm];
        }
        #pragma unroll
        for (int i = 0; i < 4; i++) {
            int idx = tid + i * 256;
            int n = idx >> 4, kk = idx & 15;        // B: coalesced along f
            Bs[kk][n] = W[(size_t)(n0 + n) * F_ + f0 + kk];
        }
        __syncthreads();

        #pragma unroll
        for (int kk = 0; kk < 16; kk++) {
            float4 a = *(const float4*)&As[kk][tm4];
            float4 bb = *(const float4*)&Bs[kk][tn4];
            acc[0][0] += a.x * bb.x; acc[0][1] += a.x * bb.y; acc[0][2] += a.x * bb.z; acc[0][3] += a.x * bb.w;
            acc[1][0] += a.y * bb.x; acc[1][1] += a.y * bb.y; acc[1][2] += a.y * bb.z; acc[1][3] += a.y * bb.w;
            acc[2][0] += a.z * bb.x; acc[2][1] += a.z * bb.y; acc[2][2] += a.z * bb.z; acc[2][3] += a.z * bb.w;
            acc[3][0] += a.w * bb.x; acc[3][1] += a.w * bb.y; acc[3][2] += a.w * bb.z; acc[3][3] += a.w * bb.w;
        }
        __syncthreads();
    }

    #pragma unroll
    for (int i = 0; i < 4; i++) {
        size_t row = ((size_t)(b * T_ + t0 + tm4 + i)) * F_ + n0;
        #pragma unroll
        for (int j = 0; j < 4; j++)
            out[row + tn4 + j] = acc[i][j] + bias[n0 + tn4 + j];
    }
}

// ---------------------------------------------------------------------------
// RoPE + head permute. One block per (t,b), 128 threads: h = tid/32, f = tid%32.
// Reference: Ur = sin(U), Ui = cos(U); rot(r,i) = (r*Ur - i*Ui, r*Ui + i*Ur)
// ---------------------------------------------------------------------------
__global__ void rope_kernel()
{
    const int t = blockIdx.x, b = blockIdx.y;
    const int tid = threadIdx.x;
    const int h = tid >> 5, f = tid & 31;

    float u = (float)t * exp2f(-(float)f) * 0.0625f;
    float s, c;
    sincosf(u, &s, &c);

    const float* Qb = d_Q + ((size_t)(b * T_ + t)) * F_ + h * HF;
    const float* Kb = d_K + ((size_t)(b * T_ + t)) * F_ + h * HF;

    const size_t o = ((size_t)((b * H_ + h) * T_ + t)) * DR + f;

    float r, i;
    r = Qb[f];      i = Qb[NW + f];
    d_Q1[o] = r * s - i * c;  d_Q1[o + NW] = r * c + i * s;
    r = Qb[2*NW+f]; i = Qb[3*NW + f];
    d_Q2[o] = r * s - i * c;  d_Q2[o + NW] = r * c + i * s;
    r = Kb[f];      i = Kb[NW + f];
    d_K1[o] = r * s - i * c;  d_K1[o + NW] = r * c + i * s;
    r = Kb[2*NW+f]; i = Kb[3*NW + f];
    d_K2[o] = r * s - i * c;  d_K2[o + NW] = r * c + i * s;

    // V head permute: [B,T,H,128] -> [B,H,T,128]
    const float* Vb = d_V + ((size_t)(b * T_ + t)) * F_ + h * HF;
    float* Vo = d_Vh + ((size_t)((b * H_ + h) * T_ + t)) * HF;
    #pragma unroll
    for (int j = 0; j < 4; j++)
        Vo[f + j * 32] = Vb[f + j * 32];
}

// ---------------------------------------------------------------------------
// Fused scores: S1 = Q1 K1^T / 16, S2 = Q2 K2^T / 16  per (b,h).
// 64x64 tile over (q,k), BK=16 over d=64, 256 threads, 4x4 microtile x2.
// ---------------------------------------------------------------------------
__global__ void scores_gemm()
{
    const int bh = blockIdx.z;
    const int q0 = blockIdx.x * 64;
    const int k0 = blockIdx.y * 64;

    __shared__ float Q1s[16][68], K1s[16][68], Q2s[16][68], K2s[16][68];

    const int tid = threadIdx.x;
    const int tm4 = (tid & 15) * 4;
    const int tn4 = (tid >> 4) * 4;

    const float* q1 = d_Q1 + (size_t)bh * T_ * DR;
    const float* q2 = d_Q2 + (size_t)bh * T_ * DR;
    const float* k1 = d_K1 + (size_t)bh * T_ * DR;
    const float* k2 = d_K2 + (size_t)bh * T_ * DR;

    float acc1[4][4] = {}, acc2[4][4] = {};

    for (int d0 = 0; d0 < DR; d0 += 16) {
        #pragma unroll
        for (int i = 0; i < 4; i++) {
            int idx = tid + i * 256;
            int m = idx >> 4, kk = idx & 15;        // coalesced along d
            Q1s[kk][m] = q1[(size_t)(q0 + m) * DR + d0 + kk];
            K1s[kk][m] = k1[(size_t)(k0 + m) * DR + d0 + kk];
            Q2s[kk][m] = q2[(size_t)(q0 + m) * DR + d0 + kk];
            K2s[kk][m] = k2[(size_t)(k0 + m) * DR + d0 + kk];
        }
        __syncthreads();

        #pragma unroll
        for (int kk = 0; kk < 16; kk++) {
            float4 a1 = *(const float4*)&Q1s[kk][tm4];
            float4 b1 = *(const float4*)&K1s[kk][tn4];
            float4 a2 = *(const float4*)&Q2s[kk][tm4];
            float4 b2 = *(const float4*)&K2s[kk][tn4];
            acc1[0][0] += a1.x*b1.x; acc1[0][1] += a1.x*b1.y; acc1[0][2] += a1.x*b1.z; acc1[0][3] += a1.x*b1.w;
            acc1[1][0] += a1.y*b1.x; acc1[1][1] += a1.y*b1.y; acc1[1][2] += a1.y*b1.z; acc1[1][3] += a1.y*b1.w;
            acc1[2][0] += a1.z*b1.x; acc1[2][1] += a1.z*b1.y; acc1[2][2] += a1.z*b1.z; acc1[2][3] += a1.z*b1.w;
            acc1[3][0] += a1.w*b1.x; acc1[3][1] += a1.w*b1.y; acc1[3][2] += a1.w*b1.z; acc1[3][3] += a1.w*b1.w;
            acc2[0][0] += a2.x*b2.x; acc2[0][1] += a2.x*b2.y; acc2[0][2] += a2.x*b2.z; acc2[0][3] += a2.x*b2.w;
            acc2[1][0] += a2.y*b2.x; acc2[1][1] += a2.y*b2.y; acc2[1][2] += a2.y*b2.z; acc2[1][3] += a2.y*b2.w;
            acc2[2][0] += a2.z*b2.x; acc2[2][1] += a2.z*b2.y; acc2[2][2] += a2.z*b2.z; acc2[2][3] += a2.z*b2.w;
            acc2[3][0] += a2.w*b2.x; acc2[3][1] += a2.w*b2.y; acc2[3][2] += a2.w*b2.z; acc2[3][3] += a2.w*b2.w;
        }
        __syncthreads();
    }

    const float sc = 0.0625f;   // 1/sqrt(F/2) = 1/16
    float* s1o = d_S1 + (size_t)bh * T_ * T_;
    float* s2o = d_S2 + (size_t)bh * T_ * T_;
    #pragma unroll
    for (int i = 0; i < 4; i++) {
        size_t row = (size_t)(q0 + tm4 + i) * T_ + k0;
        #pragma unroll
        for (int j = 0; j < 4; j++) {
            s1o[row + tn4 + j] = acc1[i][j] * sc;
            s2o[row + tn4 + j] = acc2[i][j] * sc;
        }
    }
}

// ---------------------------------------------------------------------------
// Softmax of S1 and S2 rows, combine A = softmax(S1) - s2[h]*softmax(S2),
// written in place over S1. One block per (q, bh), 256 threads.
// ---------------------------------------------------------------------------
__global__ void softmax_combine(const float* __restrict__ s2v)
{
    const int q  = blockIdx.x;
    const int bh = blockIdx.y;
    const int h  = bh & (H_ - 1);
    const int tid = threadIdx.x;

    __shared__ float r1[T_];
    __shared__ float r2[T_];
    __shared__ float red[8];
    __shared__ float bcast;

    float* row1 = d_S1 + ((size_t)bh * T_ + q) * T_;
    const float* row2 = d_S2 + ((size_t)bh * T_ + q) * T_;

    for (int k = tid; k < T_; k += 256) { r1[k] = row1[k]; r2[k] = row2[k]; }
    __syncthreads();

    const int lane = tid & 31, warp = tid >> 5;

    // --- max/sum helper expanded inline for both rows ---
    float m1 = -1e30f, m2 = -1e30f;
    for (int k = tid; k < T_; k += 256) { m1 = fmaxf(m1, r1[k]); m2 = fmaxf(m2, r2[k]); }
    #pragma unroll
    for (int off = 16; off; off >>= 1) {
        m1 = fmaxf(m1, __shfl_xor_sync(0xffffffffu, m1, off));
        m2 = fmaxf(m2, __shfl_xor_sync(0xffffffffu, m2, off));
    }
    if (lane == 0) red[warp] = m1;
    __syncthreads();
    if (tid == 0) { float m = red[0]; for (int w = 1; w < 8; w++) m = fmaxf(m, red[w]); bcast = m; }
    __syncthreads();
    m1 = bcast;
    __syncthreads();
    if (lane == 0) red[warp] = m2;
    __syncthreads();
    if (tid == 0) { float m = red[0]; for (int w = 1; w < 8; w++) m = fmaxf(m, red[w]); bcast = m; }
    __syncthreads();
    m2 = bcast;
    __syncthreads();

    float l1 = 0.f, l2 = 0.f;
    for (int k = tid; k < T_; k += 256) { l1 += expf(r1[k] - m1); l2 += expf(r2[k] - m2); }
    #pragma unroll
    for (int off = 16; off; off >>= 1) {
        l1 += __shfl_xor_sync(0xffffffffu, l1, off);
        l2 += __shfl_xor_sync(0xffffffffu, l2, off);
    }
    if (lane == 0) red[warp] = l1;
    __syncthreads();
    if (tid == 0) { float s = 0.f; for (int w = 0; w < 8; w++) s += red[w]; bcast = s; }
    __syncthreads();
    l1 = bcast;
    __syncthreads();
    if (lane == 0) red[warp] = l2;
    __syncthreads();
    if (tid == 0) { float s = 0.f; for (int w = 0; w < 8; w++) s += red[w]; bcast = s; }
    __syncthreads();
    l2 = bcast;

    const float inv1 = 1.f / l1;
    const float inv2 = s2v[h] / l2;
    for (int k = tid; k < T_; k += 256)
        row1[k] = expf(r1[k] - m1) * inv1 - expf(r2[k] - m2) * inv2;
}

// ---------------------------------------------------------------------------
// R = A @ V per (b,h):  M=T, N=128, K=T.  Writes straight into [B,T,F] layout.
// ---------------------------------------------------------------------------
__global__ void av_gemm()
{
    const int bh = blockIdx.z;
    const int q0 = blockIdx.x * 64;
    const int n0 = blockIdx.y * 64;
    const int b = bh >> 2, h = bh & 3;

    __shared__ float As[16][68];
    __shared__ float Bs[16][68];

    const int tid = threadIdx.x;
    const int tm4 = (tid & 15) * 4;
    const int tn4 = (tid >> 4) * 4;

    const float* A = d_S1 + (size_t)bh * T_ * T_;
    const float* V = d_Vh + (size_t)bh * T_ * HF;

    float acc[4][4] = {};

    for (int k0 = 0; k0 < T_; k0 += 16) {
        #pragma unroll
        for (int i = 0; i < 4; i++) {
            int idx = tid + i * 256;
            int m = idx >> 4, kk = idx & 15;        // A: coalesced along k
            As[kk][m] = A[(size_t)(q0 + m) * T_ + k0 + kk];
        }
        #pragma unroll
        for (int i = 0; i < 4; i++) {
            int idx = tid + i * 256;
            int kk = idx >> 6, n = idx & 63;        // V: coalesced along n
            Bs[kk][n] = V[(size_t)(k0 + kk) * HF + n0 + n];
        }
        __syncthreads();

        #pragma unroll
        for (int kk = 0; kk < 16; kk++) {
            float4 a = *(const float4*)&As[kk][tm4];
            float4 bb = *(const float4*)&Bs[kk][tn4];
            acc[0][0] += a.x * bb.x; acc[0][1] += a.x * bb.y; acc[0][2] += a.x * bb.z; acc[0][3] += a.x * bb.w;
            acc[1][0] += a.y * bb.x; acc[1][1] += a.y * bb.y; acc[1][2] += a.y * bb.z; acc[1][3] += a.y * bb.w;
            acc[2][0] += a.z * bb.x; acc[2][1] += a.z * bb.y; acc[2][2] += a.z * bb.z; acc[2][3] += a.z * bb.w;
            acc[3][0] += a.w * bb.x; acc[3][1] += a.w * bb.y; acc[3][2] += a.w * bb.z; acc[3][3] += a.w * bb.w;
        }
        __syncthreads();
    }

    #pragma unroll
    for (int i = 0; i < 4; i++) {
        size_t row = ((size_t)(b * T_ + q0 + tm4 + i)) * F_ + h * HF + n0;
        #pragma unroll
        for (int j = 0; j < 4; j++)
            d_R[row + tn4 + j] = acc[i][j];
    }
}

// ---------------------------------------------------------------------------
// out[b,f,t] = x[b,f,t] + R[b,t,f]  (shared-memory transpose)
// ---------------------------------------------------------------------------
__global__ void add_transpose(const float* __restrict__ x, float* __restrict__ out)
{
    const int b  = blockIdx.z;
    const int f0 = blockIdx.x * 32;
    const int t0 = blockIdx.y * 32;

    __shared__ float tile[32][33];
    const int tx = threadIdx.x, ty = threadIdx.y;

    #pragma unroll
    for (int j = 0; j < 4; j++) {
        int tt = ty + j * 8;
        tile[tt][tx] = d_R[((size_t)(b * T_ + t0 + tt)) * F_ + f0 + tx];
    }
    __syncthreads();
    #pragma unroll
    for (int j = 0; j < 4; j++) {
        int ff = ty + j * 8;
        size_t o = ((size_t)(b * F_ + f0 + ff)) * T_ + t0 + tx;
        out[o] = x[o] + tile[tx][ff];
    }
}

// ---------------------------------------------------------------------------
extern "C" void kernel_launch(void* const* d_in, const int* in_sizes, int n_in,
                              void* d_out, int out_size)
{
    const float* x  = (const float*)d_in[0];
    const float* Wq = (const float*)d_in[1];
    const float* bq = (const float*)d_in[2];
    const float* Wk = (const float*)d_in[3];
    const float* bk = (const float*)d_in[4];
    const float* Wv = (const float*)d_in[5];
    const float* bv = (const float*)d_in[6];
    const float* s2 = (const float*)d_in[7];
    float* out = (float*)d_out;

    dim3 gP(T_ / 64, F_ / 64, B_);
    qkv_gemm<<<gP, 256>>>(x, Wq, bq, 0);
    qkv_gemm<<<gP, 256>>>(x, Wk, bk, 1);
    qkv_gemm<<<gP, 256>>>(x, Wv, bv, 2);

    rope_kernel<<<dim3(T_, B_), 128>>>();

    scores_gemm<<<dim3(T_ / 64, T_ / 64, B_ * H_), 256>>>();

    softmax_combine<<<dim3(T_, B_ * H_), 256>>>(s2);

    av_gemm<<<dim3(T_ / 64, HF / 64, B_ * H_), 256>>>();

    add_transpose<<<dim3(F_ / 32, T_ / 32, B_), dim3(32, 8)>>>(x, out);
}

// round 2
// speedup vs baseline: 2.0010x; 2.0010x over previous
#include <cuda_runtime.h>
#include <math.h>

#define B_  4
#define F_  512
#define T_  2048
#define H_  4
#define HF  128   // F_/H_
#define DR  64    // rotated head dim (2*32)
#define NW  32    // quarter width

// GEMM tiling
#define BM  128
#define BN  128
#define BK  16
#define LDA 20    // padded row stride (floats): BK + 4 -> conflict-free LDSM

// ---------------- scratch (device globals; no allocation allowed) ----------
__device__ float d_Q [B_*T_*F_];
__device__ float d_K [B_*T_*F_];
__device__ float d_V [B_*T_*F_];
__device__ float d_Q1[B_*H_*T_*DR];   // pre-scaled by 1/16
__device__ float d_Q2[B_*H_*T_*DR];   // pre-scaled by 1/16
__device__ float d_K1[B_*H_*T_*DR];
__device__ float d_K2[B_*H_*T_*DR];
__device__ float d_Vh[B_*H_*T_*HF];
__device__ float d_S1[(size_t)B_*H_*T_*T_];   // holds A after softmax_combine
__device__ float d_S2[(size_t)B_*H_*T_*T_];
__device__ float d_R [B_*T_*F_];

// ---------------------------------------------------------------------------
// tf32 mma helpers
// ---------------------------------------------------------------------------
__device__ __forceinline__ unsigned f2tf32(float f) {
    unsigned r; asm("cvt.rna.tf32.f32 %0, %1;" : "=r"(r) : "f"(f)); return r;
}
__device__ __forceinline__ void ldsm_x4(unsigned addr, unsigned &r0, unsigned &r1,
                                        unsigned &r2, unsigned &r3) {
    asm volatile("ldmatrix.sync.aligned.m8n8.x4.shared.b16 {%0,%1,%2,%3}, [%4];"
                 : "=r"(r0), "=r"(r1), "=r"(r2), "=r"(r3) : "r"(addr));
}
__device__ __forceinline__ void ldsm_x2(unsigned addr, unsigned &r0, unsigned &r1) {
    asm volatile("ldmatrix.sync.aligned.m8n8.x2.shared.b16 {%0,%1}, [%2];"
                 : "=r"(r0), "=r"(r1) : "r"(addr));
}
__device__ __forceinline__ void mma_tf32(float c[4], unsigned a0, unsigned a1,
                                         unsigned a2, unsigned a3,
                                         unsigned b0, unsigned b1) {
    asm volatile("mma.sync.aligned.m16n8k8.row.col.f32.tf32.tf32.f32 "
                 "{%0,%1,%2,%3},{%4,%5,%6,%7},{%8,%9},{%0,%1,%2,%3};"
                 : "+f"(c[0]), "+f"(c[1]), "+f"(c[2]), "+f"(c[3])
                 : "r"(a0), "r"(a1), "r"(a2), "r"(a3), "r"(b0), "r"(b1));
}

// Per-lane LDSM source addresses.
// A tile stored As[m][k] (row stride LDA floats); x4 loads one m16 x k8 fragment.
__device__ __forceinline__ unsigned lane_a_addr(const unsigned* As, int wm, int lane) {
    int m = wm * 32 + (lane & 7) + ((lane >> 3) & 1) * 8;
    int k = (lane >> 4) * 4;
    return (unsigned)__cvta_generic_to_shared(As + m * LDA + k);
}
// B tile stored Bs[n][k]; x2 loads one n8 x k8 fragment (b0: k0..3, b1: k4..7).
__device__ __forceinline__ unsigned lane_b_addr(const unsigned* Bs, int wn, int lane) {
    int n = wn * 64 + (lane & 7);
    int k = ((lane >> 3) & 1) * 4;
    return (unsigned)__cvta_generic_to_shared(Bs + n * LDA + k);
}

// One BK=16 stage of the 32x64 warp tile: acc[mi][ni][4]
__device__ __forceinline__ void mma_stage(unsigned aAddr, unsigned bAddr,
                                          float (&acc)[2][8][4]) {
#pragma unroll
    for (int ks = 0; ks < 2; ks++) {
        unsigned a0[4], a1[4];
        ldsm_x4(aAddr + ks * 32,                  a0[0], a0[1], a0[2], a0[3]);
        ldsm_x4(aAddr + 16 * LDA * 4 + ks * 32,   a1[0], a1[1], a1[2], a1[3]);
#pragma unroll
        for (int ni = 0; ni < 8; ni++) {
            unsigned b0, b1;
            ldsm_x2(bAddr + ni * 8 * LDA * 4 + ks * 32, b0, b1);
            mma_tf32(acc[0][ni], a0[0], a0[1], a0[2], a0[3], b0, b1);
            mma_tf32(acc[1][ni], a1[0], a1[1], a1[2], a1[3], b0, b1);
        }
    }
}

// ---------------------------------------------------------------------------
// QKV projection (tf32): out[b,t,n] = sum_f x[b,f,t] * W[n,f] + bias[n]
// grid (T/128, F/128, B), 256 threads
// ---------------------------------------------------------------------------
__global__ void qkv_tf32(const float* __restrict__ x, const float* __restrict__ W,
                         const float* __restrict__ bias, int sel)
{
    float* out = (sel == 0) ? d_Q : (sel == 1) ? d_K : d_V;
    const int b  = blockIdx.z;
    const int t0 = blockIdx.x * BM;
    const int n0 = blockIdx.y * BN;

    __shared__ __align__(16) unsigned As[BM * LDA];
    __shared__ __align__(16) unsigned Bs[BN * LDA];

    const int tid = threadIdx.x, lane = tid & 31, wid = tid >> 5;
    const int wm = wid & 3, wn = wid >> 2;

    float acc[2][8][4] = {};
    const unsigned aAddr = lane_a_addr(As, wm, lane);
    const unsigned bAddr = lane_b_addr(Bs, wn, lane);

    const float* xb = x + (size_t)b * F_ * T_;

    for (int f0 = 0; f0 < F_; f0 += BK) {
#pragma unroll
        for (int i = 0; i < 8; i++) {          // A: 128m x 16k, coalesced along t
            int idx = tid + i * 256;
            int m = idx & 127, k = idx >> 7;
            As[m * LDA + k] = f2tf32(xb[(size_t)(f0 + k) * T_ + t0 + m]);
        }
#pragma unroll
        for (int i = 0; i < 8; i++) {          // B: 128n x 16k, coalesced along f
            int idx = tid + i * 256;
            int k = idx & 15, n = idx >> 4;
            Bs[n * LDA + k] = f2tf32(W[(size_t)(n0 + n) * F_ + f0 + k]);
        }
        __syncthreads();
        mma_stage(aAddr, bAddr, acc);
        __syncthreads();
    }

    const int g = lane >> 2, tig = lane & 3;
#pragma unroll
    for (int mi = 0; mi < 2; mi++) {
        int row = t0 + wm * 32 + mi * 16 + g;
#pragma unroll
        for (int ni = 0; ni < 8; ni++) {
            int col = n0 + wn * 64 + ni * 8 + tig * 2;
            float b0v = bias[col], b1v = bias[col + 1];
            float2 v0 = { acc[mi][ni][0] + b0v, acc[mi][ni][1] + b1v };
            float2 v1 = { acc[mi][ni][2] + b0v, acc[mi][ni][3] + b1v };
            *(float2*)&out[((size_t)(b * T_ + row)) * F_ + col] = v0;
            *(float2*)&out[((size_t)(b * T_ + row + 8)) * F_ + col] = v1;
        }
    }
}

// ---------------------------------------------------------------------------
// RoPE + head permute; Q outputs pre-scaled by 1/16 (score scale folded in).
// ---------------------------------------------------------------------------
__global__ void rope_kernel()
{
    const int t = blockIdx.x, b = blockIdx.y;
    const int tid = threadIdx.x;
    const int h = tid >> 5, f = tid & 31;

    float u = (float)t * exp2f(-(float)f) * 0.0625f;
    float s, c;
    sincosf(u, &s, &c);

    const float* Qb = d_Q + ((size_t)(b * T_ + t)) * F_ + h * HF;
    const float* Kb = d_K + ((size_t)(b * T_ + t)) * F_ + h * HF;

    const size_t o = ((size_t)((b * H_ + h) * T_ + t)) * DR + f;
    const float qs = 0.0625f;   // 1/sqrt(F/2)

    float r, i;
    r = Qb[f];      i = Qb[NW + f];
    d_Q1[o] = (r * s - i * c) * qs;  d_Q1[o + NW] = (r * c + i * s) * qs;
    r = Qb[2*NW+f]; i = Qb[3*NW + f];
    d_Q2[o] = (r * s - i * c) * qs;  d_Q2[o + NW] = (r * c + i * s) * qs;
    r = Kb[f];      i = Kb[NW + f];
    d_K1[o] = r * s - i * c;  d_K1[o + NW] = r * c + i * s;
    r = Kb[2*NW+f]; i = Kb[3*NW + f];
    d_K2[o] = r * s - i * c;  d_K2[o + NW] = r * c + i * s;

    const float* Vb = d_V + ((size_t)(b * T_ + t)) * F_ + h * HF;
    float* Vo = d_Vh + ((size_t)((b * H_ + h) * T_ + t)) * HF;
#pragma unroll
    for (int j = 0; j < 4; j++)
        Vo[f + j * 32] = Vb[f + j * 32];
}

// ---------------------------------------------------------------------------
// Scores (tf32): S = Q Kt^T per (b,h).  sel 0: (Q1,K1)->S1, 1: (Q2,K2)->S2
// grid (T/128, T/128, B*H), 256 threads, K loop = 64 (4 stages)
// ---------------------------------------------------------------------------
__global__ void scores_tf32(int sel)
{
    const float* Qp = sel ? d_Q2 : d_Q1;
    const float* Kp = sel ? d_K2 : d_K1;
    float*       Sp = sel ? d_S2 : d_S1;

    const int bh = blockIdx.z;
    const int q0 = blockIdx.x * BM;
    const int k0 = blockIdx.y * BN;

    __shared__ __align__(16) unsigned As[BM * LDA];
    __shared__ __align__(16) unsigned Bs[BN * LDA];

    const int tid = threadIdx.x, lane = tid & 31, wid = tid >> 5;
    const int wm = wid & 3, wn = wid >> 2;

    float acc[2][8][4] = {};
    const unsigned aAddr = lane_a_addr(As, wm, lane);
    const unsigned bAddr = lane_b_addr(Bs, wn, lane);

    const float* qb = Qp + (size_t)bh * T_ * DR;
    const float* kb = Kp + (size_t)bh * T_ * DR;

    for (int d0 = 0; d0 < DR; d0 += BK) {
#pragma unroll
        for (int i = 0; i < 8; i++) {
            int idx = tid + i * 256;
            int k = idx & 15, m = idx >> 4;
            As[m * LDA + k] = f2tf32(qb[(size_t)(q0 + m) * DR + d0 + k]);
            Bs[m * LDA + k] = f2tf32(kb[(size_t)(k0 + m) * DR + d0 + k]);
        }
        __syncthreads();
        mma_stage(aAddr, bAddr, acc);
        __syncthreads();
    }

    float* so = Sp + (size_t)bh * T_ * T_;
    const int g = lane >> 2, tig = lane & 3;
#pragma unroll
    for (int mi = 0; mi < 2; mi++) {
        int row = q0 + wm * 32 + mi * 16 + g;
#pragma unroll
        for (int ni = 0; ni < 8; ni++) {
            int col = k0 + wn * 64 + ni * 8 + tig * 2;
            *(float2*)&so[(size_t)row * T_ + col] =
                make_float2(acc[mi][ni][0], acc[mi][ni][1]);
            *(float2*)&so[(size_t)(row + 8) * T_ + col] =
                make_float2(acc[mi][ni][2], acc[mi][ni][3]);
        }
    }
}

// ---------------------------------------------------------------------------
// Softmax rows of S1,S2; A = softmax(S1) - s2[h]*softmax(S2) in place over S1.
// exp cached in smem (computed once per element).
// ---------------------------------------------------------------------------
__global__ void softmax_combine(const float* __restrict__ s2v)
{
    const int q  = blockIdx.x;
    const int bh = blockIdx.y;
    const int h  = bh & (H_ - 1);
    const int tid = threadIdx.x;

    __shared__ float r1[T_];
    __shared__ float r2[T_];
    __shared__ float red[8];
    __shared__ float bcast;

    float* row1 = d_S1 + ((size_t)bh * T_ + q) * T_;
    const float* row2 = d_S2 + ((size_t)bh * T_ + q) * T_;

    for (int k = tid; k < T_; k += 256) { r1[k] = row1[k]; r2[k] = row2[k]; }
    __syncthreads();

    const int lane = tid & 31, warp = tid >> 5;

    float m1 = -1e30f, m2 = -1e30f;
    for (int k = tid; k < T_; k += 256) { m1 = fmaxf(m1, r1[k]); m2 = fmaxf(m2, r2[k]); }
#pragma unroll
    for (int off = 16; off; off >>= 1) {
        m1 = fmaxf(m1, __shfl_xor_sync(0xffffffffu, m1, off));
        m2 = fmaxf(m2, __shfl_xor_sync(0xffffffffu, m2, off));
    }
    if (lane == 0) red[warp] = m1;
    __syncthreads();
    if (tid == 0) { float m = red[0]; for (int w = 1; w < 8; w++) m = fmaxf(m, red[w]); bcast = m; }
    __syncthreads();
    m1 = bcast;
    __syncthreads();
    if (lane == 0) red[warp] = m2;
    __syncthreads();
    if (tid == 0) { float m = red[0]; for (int w = 1; w < 8; w++) m = fmaxf(m, red[w]); bcast = m; }
    __syncthreads();
    m2 = bcast;
    __syncthreads();

    float l1 = 0.f, l2 = 0.f;
    for (int k = tid; k < T_; k += 256) {
        float e1 = expf(r1[k] - m1); r1[k] = e1; l1 += e1;
        float e2 = expf(r2[k] - m2); r2[k] = e2; l2 += e2;
    }
#pragma unroll
    for (int off = 16; off; off >>= 1) {
        l1 += __shfl_xor_sync(0xffffffffu, l1, off);
        l2 += __shfl_xor_sync(0xffffffffu, l2, off);
    }
    if (lane == 0) red[warp] = l1;
    __syncthreads();
    if (tid == 0) { float s = 0.f; for (int w = 0; w < 8; w++) s += red[w]; bcast = s; }
    __syncthreads();
    l1 = bcast;
    __syncthreads();
    if (lane == 0) red[warp] = l2;
    __syncthreads();
    if (tid == 0) { float s = 0.f; for (int w = 0; w < 8; w++) s += red[w]; bcast = s; }
    __syncthreads();
    l2 = bcast;

    const float inv1 = 1.f / l1;
    const float inv2 = s2v[h] / l2;
    for (int k = tid; k < T_; k += 256)
        row1[k] = r1[k] * inv1 - r2[k] * inv2;
}

// ---------------------------------------------------------------------------
// R = A @ V (tf32) per (b,h): M=T, N=128, K=T. grid (T/128, 1, B*H)
// ---------------------------------------------------------------------------
__global__ void av_tf32()
{
    const int bh = blockIdx.z;
    const int q0 = blockIdx.x * BM;
    const int b = bh >> 2, h = bh & 3;

    __shared__ __align__(16) unsigned As[BM * LDA];
    __shared__ __align__(16) unsigned Bs[BN * LDA];

    const int tid = threadIdx.x, lane = tid & 31, wid = tid >> 5;
    const int wm = wid & 3, wn = wid >> 2;

    float acc[2][8][4] = {};
    const unsigned aAddr = lane_a_addr(As, wm, lane);
    const unsigned bAddr = lane_b_addr(Bs, wn, lane);

    const float* A = d_S1 + (size_t)bh * T_ * T_;
    const float* V = d_Vh + (size_t)bh * T_ * HF;

    for (int k0 = 0; k0 < T_; k0 += BK) {
#pragma unroll
        for (int i = 0; i < 8; i++) {          // A: 128m x 16k, coalesced along k
            int idx = tid + i * 256;
            int k = idx & 15, m = idx >> 4;
            As[m * LDA + k] = f2tf32(A[(size_t)(q0 + m) * T_ + k0 + k]);
        }
#pragma unroll
        for (int i = 0; i < 8; i++) {          // V: 16k x 128n, coalesced along n
            int idx = tid + i * 256;
            int n = idx & 127, k = idx >> 7;
            Bs[n * LDA + k] = f2tf32(V[(size_t)(k0 + k) * HF + n]);
        }
        __syncthreads();
        mma_stage(aAddr, bAddr, acc);
        __syncthreads();
    }

    const int g = lane >> 2, tig = lane & 3;
#pragma unroll
    for (int mi = 0; mi < 2; mi++) {
        int row = q0 + wm * 32 + mi * 16 + g;
#pragma unroll
        for (int ni = 0; ni < 8; ni++) {
            int col = h * HF + wn * 64 + ni * 8 + tig * 2;
            *(float2*)&d_R[((size_t)(b * T_ + row)) * F_ + col] =
                make_float2(acc[mi][ni][0], acc[mi][ni][1]);
            *(float2*)&d_R[((size_t)(b * T_ + row + 8)) * F_ + col] =
                make_float2(acc[mi][ni][2], acc[mi][ni][3]);
        }
    }
}

// ---------------------------------------------------------------------------
// out[b,f,t] = x[b,f,t] + R[b,t,f]  (shared-memory transpose)
// ---------------------------------------------------------------------------
__global__ void add_transpose(const float* __restrict__ x, float* __restrict__ out)
{
    const int b  = blockIdx.z;
    const int f0 = blockIdx.x * 32;
    const int t0 = blockIdx.y * 32;

    __shared__ float tile[32][33];
    const int tx = threadIdx.x, ty = threadIdx.y;

#pragma unroll
    for (int j = 0; j < 4; j++) {
        int tt = ty + j * 8;
        tile[tt][tx] = d_R[((size_t)(b * T_ + t0 + tt)) * F_ + f0 + tx];
    }
    __syncthreads();
#pragma unroll
    for (int j = 0; j < 4; j++) {
        int ff = ty + j * 8;
        size_t o = ((size_t)(b * F_ + f0 + ff)) * T_ + t0 + tx;
        out[o] = x[o] + tile[tx][ff];
    }
}

// ---------------------------------------------------------------------------
extern "C" void kernel_launch(void* const* d_in, const int* in_sizes, int n_in,
                              void* d_out, int out_size)
{
    const float* x  = (const float*)d_in[0];
    const float* Wq = (const float*)d_in[1];
    const float* bq = (const float*)d_in[2];
    const float* Wk = (const float*)d_in[3];
    const float* bk = (const float*)d_in[4];
    const float* Wv = (const float*)d_in[5];
    const float* bv = (const float*)d_in[6];
    const float* s2 = (const float*)d_in[7];
    float* out = (float*)d_out;

    dim3 gP(T_ / BM, F_ / BN, B_);
    qkv_tf32<<<gP, 256>>>(x, Wq, bq, 0);
    qkv_tf32<<<gP, 256>>>(x, Wk, bk, 1);
    qkv_tf32<<<gP, 256>>>(x, Wv, bv, 2);

    rope_kernel<<<dim3(T_, B_), 128>>>();

    dim3 gS(T_ / BM, T_ / BN, B_ * H_);
    scores_tf32<<<gS, 256>>>(0);
    scores_tf32<<<gS, 256>>>(1);

    softmax_combine<<<dim3(T_, B_ * H_), 256>>>(s2);

    av_tf32<<<dim3(T_ / BM, 1, B_ * H_), 256>>>();

    add_transpose<<<dim3(F_ / 32, T_ / 32, B_), dim3(32, 8)>>>(x, out);
}

// round 3
// speedup vs baseline: 3.0794x; 1.5389x over previous
#include <cuda_runtime.h>
#include <math.h>

#define B_  4
#define F_  512
#define T_  2048
#define H_  4
#define HF  128   // F_/H_
#define DR  64    // rotated head dim (2*32)
#define NW  32    // quarter width

// QKV GEMM tiling
#define BM  128
#define BN  128
#define BK  16
#define LDA 20    // padded row stride (floats) for BK=16 tiles

// Flash tiling
#define LQ  68    // padded row stride (floats) for 64-wide tiles
#define FSN 64    // kv columns per iteration
#define OSL 132   // epilogue staging row stride

// ---------------- scratch (device globals; no allocation allowed) ----------
__device__ float d_Q [B_*T_*F_];
__device__ float d_K [B_*T_*F_];
__device__ float d_V [B_*T_*F_];
__device__ float d_Q1[B_*H_*T_*DR];   // pre-scaled by 1/16
__device__ float d_Q2[B_*H_*T_*DR];   // pre-scaled by 1/16
__device__ float d_K1[B_*H_*T_*DR];
__device__ float d_K2[B_*H_*T_*DR];
__device__ float d_Vt[B_*F_*T_];      // V transposed: [b, f, t] == [bh, hf, T]

// ---------------------------------------------------------------------------
// tf32 mma helpers
// ---------------------------------------------------------------------------
__device__ __forceinline__ unsigned f2tf32(float f) {
    unsigned r; asm("cvt.rna.tf32.f32 %0, %1;" : "=r"(r) : "f"(f)); return r;
}
__device__ __forceinline__ void ldsm_x4(unsigned addr, unsigned &r0, unsigned &r1,
                                        unsigned &r2, unsigned &r3) {
    asm volatile("ldmatrix.sync.aligned.m8n8.x4.shared.b16 {%0,%1,%2,%3}, [%4];"
                 : "=r"(r0), "=r"(r1), "=r"(r2), "=r"(r3) : "r"(addr));
}
__device__ __forceinline__ void ldsm_x2(unsigned addr, unsigned &r0, unsigned &r1) {
    asm volatile("ldmatrix.sync.aligned.m8n8.x2.shared.b16 {%0,%1}, [%2];"
                 : "=r"(r0), "=r"(r1) : "r"(addr));
}
__device__ __forceinline__ void mma_tf32(float c[4], unsigned a0, unsigned a1,
                                         unsigned a2, unsigned a3,
                                         unsigned b0, unsigned b1) {
    asm volatile("mma.sync.aligned.m16n8k8.row.col.f32.tf32.tf32.f32 "
                 "{%0,%1,%2,%3},{%4,%5,%6,%7},{%8,%9},{%0,%1,%2,%3};"
                 : "+f"(c[0]), "+f"(c[1]), "+f"(c[2]), "+f"(c[3])
                 : "r"(a0), "r"(a1), "r"(a2), "r"(a3), "r"(b0), "r"(b1));
}

// A-tile (row-major [m][k], stride LDA) LDSM source for a m16xk8 x4 load
__device__ __forceinline__ unsigned lane_a_addr(const unsigned* As, int wm, int lane) {
    int m = wm * 32 + (lane & 7) + ((lane >> 3) & 1) * 8;
    int k = (lane >> 4) * 4;
    return (unsigned)__cvta_generic_to_shared(As + m * LDA + k);
}
// B-tile ([n][k], stride LDA) LDSM source for a n8xk8 x2 load
__device__ __forceinline__ unsigned lane_b_addr(const unsigned* Bs, int wn, int lane) {
    int n = wn * 64 + (lane & 7);
    int k = ((lane >> 3) & 1) * 4;
    return (unsigned)__cvta_generic_to_shared(Bs + n * LDA + k);
}

// One BK=16 stage of the 32x64 warp tile (QKV kernel)
__device__ __forceinline__ void mma_stage(unsigned aAddr, unsigned bAddr,
                                          float (&acc)[2][8][4]) {
#pragma unroll
    for (int ks = 0; ks < 2; ks++) {
        unsigned a0[4], a1[4];
        ldsm_x4(aAddr + ks * 32,                  a0[0], a0[1], a0[2], a0[3]);
        ldsm_x4(aAddr + 16 * LDA * 4 + ks * 32,   a1[0], a1[1], a1[2], a1[3]);
#pragma unroll
        for (int ni = 0; ni < 8; ni++) {
            unsigned b0, b1;
            ldsm_x2(bAddr + ni * 8 * LDA * 4 + ks * 32, b0, b1);
            mma_tf32(acc[0][ni], a0[0], a0[1], a0[2], a0[3], b0, b1);
            mma_tf32(acc[1][ni], a1[0], a1[1], a1[2], a1[3], b0, b1);
        }
    }
}

// ---------------------------------------------------------------------------
// QKV projection (tf32): out[b,t,n] = sum_f x[b,f,t] * W[n,f] + bias[n]
// ---------------------------------------------------------------------------
__global__ void qkv_tf32(const float* __restrict__ x, const float* __restrict__ W,
                         const float* __restrict__ bias, int sel)
{
    float* out = (sel == 0) ? d_Q : (sel == 1) ? d_K : d_V;
    const int b  = blockIdx.z;
    const int t0 = blockIdx.x * BM;
    const int n0 = blockIdx.y * BN;

    __shared__ __align__(16) unsigned As[BM * LDA];
    __shared__ __align__(16) unsigned Bs[BN * LDA];

    const int tid = threadIdx.x, lane = tid & 31, wid = tid >> 5;
    const int wm = wid & 3, wn = wid >> 2;

    float acc[2][8][4] = {};
    const unsigned aAddr = lane_a_addr(As, wm, lane);
    const unsigned bAddr = lane_b_addr(Bs, wn, lane);

    const float* xb = x + (size_t)b * F_ * T_;

    for (int f0 = 0; f0 < F_; f0 += BK) {
#pragma unroll
        for (int i = 0; i < 8; i++) {          // A: 128m x 16k, coalesced along t
            int idx = tid + i * 256;
            int m = idx & 127, k = idx >> 7;
            As[m * LDA + k] = f2tf32(xb[(size_t)(f0 + k) * T_ + t0 + m]);
        }
#pragma unroll
        for (int i = 0; i < 8; i++) {          // B: 128n x 16k, coalesced along f
            int idx = tid + i * 256;
            int k = idx & 15, n = idx >> 4;
            Bs[n * LDA + k] = f2tf32(W[(size_t)(n0 + n) * F_ + f0 + k]);
        }
        __syncthreads();
        mma_stage(aAddr, bAddr, acc);
        __syncthreads();
    }

    const int g = lane >> 2, tig = lane & 3;
#pragma unroll
    for (int mi = 0; mi < 2; mi++) {
        int row = t0 + wm * 32 + mi * 16 + g;
#pragma unroll
        for (int ni = 0; ni < 8; ni++) {
            int col = n0 + wn * 64 + ni * 8 + tig * 2;
            float b0v = bias[col], b1v = bias[col + 1];
            float2 v0 = { acc[mi][ni][0] + b0v, acc[mi][ni][1] + b1v };
            float2 v1 = { acc[mi][ni][2] + b0v, acc[mi][ni][3] + b1v };
            *(float2*)&out[((size_t)(b * T_ + row)) * F_ + col] = v0;
            *(float2*)&out[((size_t)(b * T_ + row + 8)) * F_ + col] = v1;
        }
    }
}

// ---------------------------------------------------------------------------
// RoPE; Q outputs pre-scaled by 1/16 (score scale folded in).
// ---------------------------------------------------------------------------
__global__ void rope_kernel()
{
    const int t = blockIdx.x, b = blockIdx.y;
    const int tid = threadIdx.x;
    const int h = tid >> 5, f = tid & 31;

    float u = (float)t * exp2f(-(float)f) * 0.0625f;
    float s, c;
    sincosf(u, &s, &c);

    const float* Qb = d_Q + ((size_t)(b * T_ + t)) * F_ + h * HF;
    const float* Kb = d_K + ((size_t)(b * T_ + t)) * F_ + h * HF;

    const size_t o = ((size_t)((b * H_ + h) * T_ + t)) * DR + f;
    const float qs = 0.0625f;   // 1/sqrt(F/2)

    float r, i;
    r = Qb[f];      i = Qb[NW + f];
    d_Q1[o] = (r * s - i * c) * qs;  d_Q1[o + NW] = (r * c + i * s) * qs;
    r = Qb[2*NW+f]; i = Qb[3*NW + f];
    d_Q2[o] = (r * s - i * c) * qs;  d_Q2[o + NW] = (r * c + i * s) * qs;
    r = Kb[f];      i = Kb[NW + f];
    d_K1[o] = r * s - i * c;  d_K1[o + NW] = r * c + i * s;
    r = Kb[2*NW+f]; i = Kb[3*NW + f];
    d_K2[o] = r * s - i * c;  d_K2[o + NW] = r * c + i * s;
}

// ---------------------------------------------------------------------------
// V transpose: d_V [B,T,F] -> d_Vt [B,F,T]
// ---------------------------------------------------------------------------
__global__ void vt_kernel()
{
    const int b  = blockIdx.z;
    const int f0 = blockIdx.x * 32;
    const int t0 = blockIdx.y * 32;

    __shared__ float tile[32][33];
    const int tx = threadIdx.x, ty = threadIdx.y;

#pragma unroll
    for (int j = 0; j < 4; j++) {
        int tt = ty + j * 8;
        tile[tt][tx] = d_V[((size_t)(b * T_ + t0 + tt)) * F_ + f0 + tx];
    }
    __syncthreads();
#pragma unroll
    for (int j = 0; j < 4; j++) {
        int ff = ty + j * 8;
        d_Vt[((size_t)(b * F_ + f0 + ff)) * T_ + t0 + tx] = tile[tx][ff];
    }
}

// ---------------------------------------------------------------------------
// Flash branch: S = Q Kt^T (m16 x 64), online softmax, P@V accumulate
// ---------------------------------------------------------------------------
__device__ __forceinline__ void flash_branch(
    unsigned aQ, unsigned bK, unsigned aP, unsigned bV,
    unsigned* __restrict__ Ps,
    float (&O)[16][4], float (&m)[2], float (&l)[2],
    int wid, int lane)
{
    float s[8][4] = {};
#pragma unroll
    for (int kf = 0; kf < 8; kf++) {
        unsigned a0, a1, a2, a3;
        ldsm_x4(aQ + kf * 32, a0, a1, a2, a3);
#pragma unroll
        for (int nq = 0; nq < 4; nq++) {
            unsigned b0, b1, b2, b3;
            ldsm_x4(bK + nq * 16 * LQ * 4 + kf * 32, b0, b1, b2, b3);
            mma_tf32(s[2*nq],   a0, a1, a2, a3, b0, b1);
            mma_tf32(s[2*nq+1], a0, a1, a2, a3, b2, b3);
        }
    }

    // online softmax for the two rows this lane owns (g, g+8)
    float mx0 = -1e30f, mx1 = -1e30f;
#pragma unroll
    for (int nf = 0; nf < 8; nf++) {
        mx0 = fmaxf(mx0, fmaxf(s[nf][0], s[nf][1]));
        mx1 = fmaxf(mx1, fmaxf(s[nf][2], s[nf][3]));
    }
#pragma unroll
    for (int off = 1; off < 4; off <<= 1) {
        mx0 = fmaxf(mx0, __shfl_xor_sync(0xffffffffu, mx0, off));
        mx1 = fmaxf(mx1, __shfl_xor_sync(0xffffffffu, mx1, off));
    }
    float mn0 = fmaxf(m[0], mx0), mn1 = fmaxf(m[1], mx1);
    float sc0 = __expf(m[0] - mn0), sc1 = __expf(m[1] - mn1);
    m[0] = mn0; m[1] = mn1;

    const int g = lane >> 2, tig = lane & 3;
    const int r0 = wid * 16 + g;
    float rs0 = 0.f, rs1 = 0.f;
#pragma unroll
    for (int nf = 0; nf < 8; nf++) {
        float p0 = __expf(s[nf][0] - mn0), p1 = __expf(s[nf][1] - mn0);
        float p2 = __expf(s[nf][2] - mn1), p3 = __expf(s[nf][3] - mn1);
        rs0 += p0 + p1; rs1 += p2 + p3;
        int col = nf * 8 + tig * 2;
        uint2 v0 = { f2tf32(p0), f2tf32(p1) };
        uint2 v1 = { f2tf32(p2), f2tf32(p3) };
        *(uint2*)&Ps[r0 * LQ + col] = v0;
        *(uint2*)&Ps[(r0 + 8) * LQ + col] = v1;
    }
#pragma unroll
    for (int off = 1; off < 4; off <<= 1) {
        rs0 += __shfl_xor_sync(0xffffffffu, rs0, off);
        rs1 += __shfl_xor_sync(0xffffffffu, rs1, off);
    }
    l[0] = l[0] * sc0 + rs0;
    l[1] = l[1] * sc1 + rs1;

#pragma unroll
    for (int nf = 0; nf < 16; nf++) {
        O[nf][0] *= sc0; O[nf][1] *= sc0;
        O[nf][2] *= sc1; O[nf][3] *= sc1;
    }

    __syncwarp();
#pragma unroll
    for (int kf = 0; kf < 8; kf++) {
        unsigned a0, a1, a2, a3;
        ldsm_x4(aP + kf * 32, a0, a1, a2, a3);
#pragma unroll
        for (int nq = 0; nq < 8; nq++) {
            unsigned b0, b1, b2, b3;
            ldsm_x4(bV + nq * 16 * LQ * 4 + kf * 32, b0, b1, b2, b3);
            mma_tf32(O[2*nq],   a0, a1, a2, a3, b0, b1);
            mma_tf32(O[2*nq+1], a0, a1, a2, a3, b2, b3);
        }
    }
    __syncwarp();   // next branch overwrites Ps
}

// ---------------------------------------------------------------------------
// Flash attention: per (b,h, 128-row q tile); two branches, combined epilogue
// writes out[b,f,t] = x[b,f,t] + R[b,t,f] directly.
// ---------------------------------------------------------------------------
__global__ void __launch_bounds__(256, 1)
flash_kernel(const float* __restrict__ x, const float* __restrict__ s2v,
             float* __restrict__ out)
{
    extern __shared__ unsigned sm[];
    unsigned* Q1s = sm;                     // 128*LQ
    unsigned* Q2s = Q1s + 128 * LQ;
    unsigned* K1s = Q2s + 128 * LQ;         // 64*LQ
    unsigned* K2s = K1s + 64 * LQ;
    unsigned* Vs  = K2s + 64 * LQ;          // 128*LQ
    unsigned* Ps  = Vs  + 128 * LQ;         // 128*LQ
    float*    Os  = (float*)sm;             // epilogue reuse (128*OSL)

    const int tid = threadIdx.x, lane = tid & 31, wid = tid >> 5;
    const int bh = blockIdx.y, b = bh >> 2, h = bh & 3;
    const int q0 = blockIdx.x * 128;

    // --- load Q1/Q2 tiles (float4) ---
    {
        const float4* q1g = (const float4*)(d_Q1 + ((size_t)bh * T_ + q0) * DR);
        const float4* q2g = (const float4*)(d_Q2 + ((size_t)bh * T_ + q0) * DR);
#pragma unroll
        for (int i = 0; i < 8; i++) {
            int idx = tid + i * 256;
            int k4 = idx & 15, mrow = idx >> 4;
            float4 v1 = q1g[mrow * 16 + k4];
            float4 v2 = q2g[mrow * 16 + k4];
            uint4 u1 = { f2tf32(v1.x), f2tf32(v1.y), f2tf32(v1.z), f2tf32(v1.w) };
            uint4 u2 = { f2tf32(v2.x), f2tf32(v2.y), f2tf32(v2.z), f2tf32(v2.w) };
            *(uint4*)&Q1s[mrow * LQ + k4 * 4] = u1;
            *(uint4*)&Q2s[mrow * LQ + k4 * 4] = u2;
        }
    }

    float O1[16][4] = {}, O2[16][4] = {};
    float m1[2] = { -1e30f, -1e30f }, l1[2] = { 0.f, 0.f };
    float m2[2] = { -1e30f, -1e30f }, l2[2] = { 0.f, 0.f };

    // per-lane LDSM addresses
    const int am = wid * 16 + (lane & 7) + ((lane >> 3) & 1) * 8;
    const int ak = (lane >> 4) * 4;
    const unsigned aQ1 = (unsigned)__cvta_generic_to_shared(Q1s + am * LQ + ak);
    const unsigned aQ2 = (unsigned)__cvta_generic_to_shared(Q2s + am * LQ + ak);
    const unsigned aP  = (unsigned)__cvta_generic_to_shared(Ps  + am * LQ + ak);
    const int bn = (lane & 7) + ((lane >> 4) & 1) * 8;
    const int bk = ((lane >> 3) & 1) * 4;
    const unsigned bK1 = (unsigned)__cvta_generic_to_shared(K1s + bn * LQ + bk);
    const unsigned bK2 = (unsigned)__cvta_generic_to_shared(K2s + bn * LQ + bk);
    const unsigned bV  = (unsigned)__cvta_generic_to_shared(Vs  + bn * LQ + bk);

    const float* vg = d_Vt + ((size_t)(b * F_ + h * HF)) * T_;

    for (int kt = 0; kt < T_ / FSN; kt++) {
        const int k0 = kt * FSN;
        __syncthreads();   // also covers initial Q-load visibility
        // K1/K2 tiles: 64x64 each (float4)
        {
            const float4* k1g = (const float4*)(d_K1 + ((size_t)bh * T_ + k0) * DR);
            const float4* k2g = (const float4*)(d_K2 + ((size_t)bh * T_ + k0) * DR);
#pragma unroll
            for (int i = 0; i < 4; i++) {
                int idx = tid + i * 256;
                int k4 = idx & 15, n = idx >> 4;
                float4 v1 = k1g[n * 16 + k4];
                float4 v2 = k2g[n * 16 + k4];
                uint4 u1 = { f2tf32(v1.x), f2tf32(v1.y), f2tf32(v1.z), f2tf32(v1.w) };
                uint4 u2 = { f2tf32(v2.x), f2tf32(v2.y), f2tf32(v2.z), f2tf32(v2.w) };
                *(uint4*)&K1s[n * LQ + k4 * 4] = u1;
                *(uint4*)&K2s[n * LQ + k4 * 4] = u2;
            }
        }
        // V tile: Vs[n=hf 0..127][k=kv 0..63] from d_Vt (k contiguous)
        {
#pragma unroll
            for (int i = 0; i < 8; i++) {
                int idx = tid + i * 256;
                int k4 = idx & 15, n = idx >> 4;
                float4 v = *(const float4*)(vg + (size_t)n * T_ + k0 + k4 * 4);
                uint4 u = { f2tf32(v.x), f2tf32(v.y), f2tf32(v.z), f2tf32(v.w) };
                *(uint4*)&Vs[n * LQ + k4 * 4] = u;
            }
        }
        __syncthreads();

        flash_branch(aQ1, bK1, aP, bV, Ps, O1, m1, l1, wid, lane);
        flash_branch(aQ2, bK2, aP, bV, Ps, O2, m2, l2, wid, lane);
    }

    // --- epilogue: combine, transpose via smem, add x, write out ---
    __syncthreads();
    const float s2h = s2v[h];
    const int g = lane >> 2, tig = lane & 3;
    const int r0 = wid * 16 + g;
    const float i10 = 1.f / l1[0], i11 = 1.f / l1[1];
    const float i20 = s2h / l2[0], i21 = s2h / l2[1];
#pragma unroll
    for (int nf = 0; nf < 16; nf++) {
        int col = nf * 8 + tig * 2;
        Os[col * OSL + r0]           = O1[nf][0] * i10 - O2[nf][0] * i20;
        Os[(col + 1) * OSL + r0]     = O1[nf][1] * i10 - O2[nf][1] * i20;
        Os[col * OSL + r0 + 8]       = O1[nf][2] * i11 - O2[nf][2] * i21;
        Os[(col + 1) * OSL + r0 + 8] = O1[nf][3] * i11 - O2[nf][3] * i21;
    }
    __syncthreads();
#pragma unroll
    for (int i = 0; i < 16; i++) {
        int idx = tid + i * 256;
        int qv = idx & 31, n = idx >> 5;
        size_t o = ((size_t)(b * F_ + h * HF + n)) * T_ + q0 + qv * 4;
        float4 xv = *(const float4*)&x[o];
        float4 r  = *(const float4*)&Os[n * OSL + qv * 4];
        float4 ov = { xv.x + r.x, xv.y + r.y, xv.z + r.z, xv.w + r.w };
        *(float4*)&out[o] = ov;
    }
}

#define FLASH_SMEM ((128*LQ*2 + 64*LQ*2 + 128*LQ + 128*LQ) * 4)

// ---------------------------------------------------------------------------
extern "C" void kernel_launch(void* const* d_in, const int* in_sizes, int n_in,
                              void* d_out, int out_size)
{
    const float* x  = (const float*)d_in[0];
    const float* Wq = (const float*)d_in[1];
    const float* bq = (const float*)d_in[2];
    const float* Wk = (const float*)d_in[3];
    const float* bk = (const float*)d_in[4];
    const float* Wv = (const float*)d_in[5];
    const float* bv = (const float*)d_in[6];
    const float* s2 = (const float*)d_in[7];
    float* out = (float*)d_out;

    cudaFuncSetAttribute(flash_kernel,
                         cudaFuncAttributeMaxDynamicSharedMemorySize, FLASH_SMEM);

    dim3 gP(T_ / BM, F_ / BN, B_);
    qkv_tf32<<<gP, 256>>>(x, Wq, bq, 0);
    qkv_tf32<<<gP, 256>>>(x, Wk, bk, 1);
    qkv_tf32<<<gP, 256>>>(x, Wv, bv, 2);

    rope_kernel<<<dim3(T_, B_), 128>>>();
    vt_kernel<<<dim3(F_ / 32, T_ / 32, B_), dim3(32, 8)>>>();

    flash_kernel<<<dim3(T_ / 128, B_ * H_), 256, FLASH_SMEM>>>(x, s2, out);
}

// round 4
// speedup vs baseline: 3.6657x; 1.1904x over previous
#include <cuda_runtime.h>
#include <math.h>

#define B_  4
#define F_  512
#define T_  2048
#define H_  4
#define HF  128   // F_/H_
#define DR  64    // rotated head dim (2*32)

// QKV GEMM tiling
#define BM  128
#define BN  128
#define BK  16
#define LDA 20    // padded row stride (words) for BK=16 tiles

// Flash tiling
#define LQ  68    // padded row stride (words) for 64-wide tiles
#define FSN 64    // kv columns per iteration
#define NT  (T_/FSN)
#define OSL 132   // staging row stride

// ---------------- scratch (device globals; no allocation allowed) ----------
__device__ float d_Q1[B_*H_*T_*DR];   // pre-scaled by 1/16
__device__ float d_Q2[B_*H_*T_*DR];   // pre-scaled by 1/16
__device__ float d_K1[B_*H_*T_*DR];
__device__ float d_K2[B_*H_*T_*DR];
__device__ float d_Vt[B_*F_*T_];      // V transposed: [b, f, t]

// ---------------------------------------------------------------------------
// mma / ldsm / cp.async helpers
// ---------------------------------------------------------------------------
__device__ __forceinline__ void ldsm_x4(unsigned addr, unsigned &r0, unsigned &r1,
                                        unsigned &r2, unsigned &r3) {
    asm volatile("ldmatrix.sync.aligned.m8n8.x4.shared.b16 {%0,%1,%2,%3}, [%4];"
                 : "=r"(r0), "=r"(r1), "=r"(r2), "=r"(r3) : "r"(addr));
}
__device__ __forceinline__ void mma_tf32(float c[4], unsigned a0, unsigned a1,
                                         unsigned a2, unsigned a3,
                                         unsigned b0, unsigned b1) {
    asm volatile("mma.sync.aligned.m16n8k8.row.col.f32.tf32.tf32.f32 "
                 "{%0,%1,%2,%3},{%4,%5,%6,%7},{%8,%9},{%0,%1,%2,%3};"
                 : "+f"(c[0]), "+f"(c[1]), "+f"(c[2]), "+f"(c[3])
                 : "r"(a0), "r"(a1), "r"(a2), "r"(a3), "r"(b0), "r"(b1));
}
__device__ __forceinline__ void cpa16(unsigned dst, const float* src) {
    asm volatile("cp.async.cg.shared.global [%0], [%1], 16;" :: "r"(dst), "l"(src));
}
#define CP_COMMIT() asm volatile("cp.async.commit_group;")
#define CP_WAIT1()  asm volatile("cp.async.wait_group 1;" ::: "memory")

// C-fragment (m16n8 rows g/g+8, cols 2tig..2tig+1) -> A-fragment (m16k8) remap.
// Needs P[g][tig], P[g+8][tig], P[g][tig+4], P[g+8][tig+4] from quad mates.
__device__ __forceinline__ void p_frag(const float s[4], int lane,
                                       unsigned &A0, unsigned &A1,
                                       unsigned &A2, unsigned &A3) {
    int tig = lane & 3, base = lane & ~3;
    int hsl = base + (tig >> 1);
    int par = tig & 1;
    float e0 = __shfl_sync(0xffffffffu, s[0], hsl);
    float e1 = __shfl_sync(0xffffffffu, s[1], hsl);
    float g0 = __shfl_sync(0xffffffffu, s[2], hsl);
    float g1 = __shfl_sync(0xffffffffu, s[3], hsl);
    float f0 = __shfl_sync(0xffffffffu, s[0], hsl + 2);
    float f1 = __shfl_sync(0xffffffffu, s[1], hsl + 2);
    float h0 = __shfl_sync(0xffffffffu, s[2], hsl + 2);
    float h1 = __shfl_sync(0xffffffffu, s[3], hsl + 2);
    A0 = __float_as_uint(par ? e1 : e0);
    A1 = __float_as_uint(par ? g1 : g0);
    A2 = __float_as_uint(par ? f1 : f0);
    A3 = __float_as_uint(par ? h1 : h0);
}

// ---------------------------------------------------------------------------
// Fused QKV projection + rope (Q,K) + transpose (V).
// grid (T/128, F/128, 3*B); n-tile == head. out[b,t,n] = x^T W^T + bias
// ---------------------------------------------------------------------------
__global__ void qkv_fused(const float* __restrict__ x,
                          const float* __restrict__ Wq, const float* __restrict__ bq,
                          const float* __restrict__ Wk, const float* __restrict__ bk,
                          const float* __restrict__ Wv, const float* __restrict__ bv)
{
    const int zz = blockIdx.z;
    const int mat = zz >> 2, b = zz & 3;
    const float* W    = (mat == 0) ? Wq : (mat == 1) ? Wk : Wv;
    const float* bias = (mat == 0) ? bq : (mat == 1) ? bk : bv;

    const int t0 = blockIdx.x * BM;
    const int h  = blockIdx.y;          // head (BN == HF)
    const int n0 = h * BN;

    __shared__ __align__(16) unsigned smq[BM * LDA * 2];
    unsigned* As = smq;
    unsigned* Bs = smq + BM * LDA;

    const int tid = threadIdx.x, lane = tid & 31, wid = tid >> 5;
    const int wm = wid & 3, wn = wid >> 2;
    const int g = lane >> 2, tig = lane & 3;

    float acc[2][8][4] = {};
    // ldsm lane addresses
    const int am = wm * 32 + (lane & 7) + ((lane >> 3) & 1) * 8;
    const int ak = (lane >> 4) * 4;
    const unsigned aAddr = (unsigned)__cvta_generic_to_shared(As + am * LDA + ak);
    const int bn = wn * 64 + (lane & 7);
    const int bk2 = ((lane >> 3) & 1) * 4;
    const unsigned bAddr = (unsigned)__cvta_generic_to_shared(Bs + bn * LDA + bk2);

    const float* xb = x + (size_t)b * F_ * T_;

    for (int f0 = 0; f0 < F_; f0 += BK) {
#pragma unroll
        for (int i = 0; i < 8; i++) {          // A: coalesced along t
            int idx = tid + i * 256;
            int m = idx & 127, k = idx >> 7;
            As[m * LDA + k] = __float_as_uint(xb[(size_t)(f0 + k) * T_ + t0 + m]);
        }
#pragma unroll
        for (int i = 0; i < 8; i++) {          // B: coalesced along f
            int idx = tid + i * 256;
            int k = idx & 15, n = idx >> 4;
            Bs[n * LDA + k] = __float_as_uint(W[(size_t)(n0 + n) * F_ + f0 + k]);
        }
        __syncthreads();
#pragma unroll
        for (int ks = 0; ks < 2; ks++) {
            unsigned a0[4], a1[4];
            ldsm_x4(aAddr + ks * 32,                a0[0], a0[1], a0[2], a0[3]);
            ldsm_x4(aAddr + 16 * LDA * 4 + ks * 32, a1[0], a1[1], a1[2], a1[3]);
#pragma unroll
            for (int ni = 0; ni < 8; ni++) {
                unsigned b0, b1, bu2, bu3;
                // x2 pattern via x4 halves not needed; reuse x2-style: load via ldsm x4 every other
                asm volatile("ldmatrix.sync.aligned.m8n8.x2.shared.b16 {%0,%1}, [%2];"
                             : "=r"(b0), "=r"(b1)
                             : "r"(bAddr + ni * 8 * LDA * 4 + ks * 32));
                (void)bu2; (void)bu3;
                mma_tf32(acc[0][ni], a0[0], a0[1], a0[2], a0[3], b0, b1);
                mma_tf32(acc[1][ni], a1[0], a1[1], a1[2], a1[3], b0, b1);
            }
        }
        __syncthreads();
    }

    // bias add (col depends on ni, parity only)
    float bcol[8][2];
#pragma unroll
    for (int ni = 0; ni < 8; ni++) {
        int col = n0 + wn * 64 + ni * 8 + tig * 2;
        bcol[ni][0] = bias[col];
        bcol[ni][1] = bias[col + 1];
    }
#pragma unroll
    for (int mi = 0; mi < 2; mi++)
#pragma unroll
        for (int ni = 0; ni < 8; ni++)
#pragma unroll
            for (int j = 0; j < 4; j++)
                acc[mi][ni][j] += bcol[ni][j & 1];

    if (mat < 2) {
        // --- rope epilogue: wn=0 -> chunk 1, wn=1 -> chunk 2 ---
        float* dst = (mat == 0) ? (wn ? d_Q2 : d_Q1) : (wn ? d_K2 : d_K1);
        const float qs = (mat == 0) ? 0.0625f : 1.0f;
        const int bh = b * H_ + h;
        float df[4][2];
#pragma unroll
        for (int ni = 0; ni < 4; ni++) {
            df[ni][0] = exp2f(-(float)(ni * 8 + tig * 2)) * 0.0625f;
            df[ni][1] = exp2f(-(float)(ni * 8 + tig * 2 + 1)) * 0.0625f;
        }
#pragma unroll
        for (int mi = 0; mi < 2; mi++) {
            int r0 = t0 + wm * 32 + mi * 16 + g;
#pragma unroll
            for (int rr = 0; rr < 2; rr++) {
                int t = r0 + rr * 8;
                size_t rowo = ((size_t)bh * T_ + t) * DR;
#pragma unroll
                for (int ni = 0; ni < 4; ni++) {
                    float o1[2], o2[2];
#pragma unroll
                    for (int e = 0; e < 2; e++) {
                        int j = rr * 2 + e;
                        float rv = acc[mi][ni][j], iv = acc[mi][ni + 4][j];
                        float u = (float)t * df[ni][e];
                        float sn, cs;
                        sincosf(u, &sn, &cs);
                        o1[e] = (rv * sn - iv * cs) * qs;
                        o2[e] = (rv * cs + iv * sn) * qs;
                    }
                    int f = ni * 8 + tig * 2;
                    *(float2*)&dst[rowo + f]      = make_float2(o1[0], o1[1]);
                    *(float2*)&dst[rowo + f + 32] = make_float2(o2[0], o2[1]);
                }
            }
        }
    } else {
        // --- V epilogue: write transposed to d_Vt[b][f][t] via smem staging ---
        float* stage = (float*)smq;   // 32 x OSL
#pragma unroll
        for (int c4 = 0; c4 < 4; c4++) {
            __syncthreads();
            if (wn == (c4 >> 1)) {
                int nbase = (c4 & 1) * 4;
#pragma unroll
                for (int mi = 0; mi < 2; mi++)
#pragma unroll
                    for (int nn = 0; nn < 4; nn++) {
                        int ni = nbase + nn;
                        int cl = nn * 8 + tig * 2;
#pragma unroll
                        for (int j = 0; j < 4; j++) {
                            int rloc = wm * 32 + mi * 16 + g + (j >> 1) * 8;
                            stage[(cl + (j & 1)) * OSL + rloc] = acc[mi][ni][j];
                        }
                    }
            }
            __syncthreads();
#pragma unroll
            for (int i = 0; i < 4; i++) {
                int idx = tid + i * 256;
                int fr = idx >> 5, t4 = (idx & 31) * 4;
                float4 v = *(float4*)&stage[fr * OSL + t4];
                *(float4*)&d_Vt[((size_t)(b * F_ + n0 + c4 * 32 + fr)) * T_ + t0 + t4] = v;
            }
        }
    }
}

// ---------------------------------------------------------------------------
// Flash attention: two branches, online softmax, shared V fragments,
// register P via quad shuffles, cp.async double-buffered K/V.
// ---------------------------------------------------------------------------
__device__ __forceinline__ void load_stage(unsigned stBase, const float* k1g,
                                           const float* k2g, const float* vgk,
                                           int tid)
{
#pragma unroll
    for (int i = 0; i < 4; i++) {
        int c = tid + i * 256;
        int row = c >> 4, cc = (c & 15) * 4;
        cpa16(stBase + (row * LQ + cc) * 4, k1g + (size_t)row * DR + cc);
    }
#pragma unroll
    for (int i = 0; i < 4; i++) {
        int c = tid + i * 256;
        int row = c >> 4, cc = (c & 15) * 4;
        cpa16(stBase + ((64 + row) * LQ + cc) * 4, k2g + (size_t)row * DR + cc);
    }
#pragma unroll
    for (int i = 0; i < 8; i++) {
        int c = tid + i * 256;
        int row = c >> 4, cc = (c & 15) * 4;
        cpa16(stBase + ((128 + row) * LQ + cc) * 4, vgk + (size_t)row * T_ + cc);
    }
}

__global__ void __launch_bounds__(256, 1)
flash_kernel(const float* __restrict__ x, const float* __restrict__ s2v,
             float* __restrict__ out)
{
    extern __shared__ float sm[];
    const unsigned sb = (unsigned)__cvta_generic_to_shared(sm);

    const int tid = threadIdx.x, lane = tid & 31, wid = tid >> 5;
    const int bh = blockIdx.y, b = bh >> 2, h = bh & 3;
    const int q0 = blockIdx.x * 128;

    const float* q1g = d_Q1 + ((size_t)bh * T_ + q0) * DR;
    const float* q2g = d_Q2 + ((size_t)bh * T_ + q0) * DR;
    const float* k1b = d_K1 + (size_t)bh * T_ * DR;
    const float* k2b = d_K2 + (size_t)bh * T_ * DR;
    const float* vg  = d_Vt + ((size_t)(b * F_ + h * HF)) * T_;

    // prologue: Q (group 0, with stage 0) then stage 1
#pragma unroll
    for (int i = 0; i < 8; i++) {
        int c = tid + i * 256;
        int row = c >> 4, cc = (c & 15) * 4;
        cpa16(sb + (row * LQ + cc) * 4, q1g + (size_t)row * DR + cc);
        cpa16(sb + ((128 + row) * LQ + cc) * 4, q2g + (size_t)row * DR + cc);
    }
    const unsigned st[2] = { sb + 256 * LQ * 4, sb + 512 * LQ * 4 };
    load_stage(st[0], k1b, k2b, vg, tid);
    CP_COMMIT();
    load_stage(st[1], k1b + (size_t)FSN * DR, k2b + (size_t)FSN * DR, vg + FSN, tid);
    CP_COMMIT();

    float O1[16][4] = {}, O2[16][4] = {};
    float m1[2] = { -1e30f, -1e30f }, l1[2] = { 0.f, 0.f };
    float m2[2] = { -1e30f, -1e30f }, l2[2] = { 0.f, 0.f };

    // ldsm lane addresses
    const int am = wid * 16 + (lane & 7) + ((lane >> 3) & 1) * 8;
    const int ak = (lane >> 4) * 4;
    const unsigned aQ1 = sb + (am * LQ + ak) * 4;
    const unsigned aQ2 = aQ1 + 128 * LQ * 4;
    const int bn = (lane & 7) + ((lane >> 4) & 1) * 8;
    const int bk = ((lane >> 3) & 1) * 4;
    const unsigned bOff = (unsigned)(bn * LQ + bk) * 4;

    for (int kt = 0; kt < NT; kt++) {
        const int cur = kt & 1;
        CP_WAIT1();
        __syncthreads();

        const unsigned bK1c = st[cur] + bOff;
        const unsigned bK2c = bK1c + 64 * LQ * 4;
        const unsigned bVc  = bK1c + 128 * LQ * 4;

        // ---- S = Q Kt^T, both branches ----
        float s1[8][4] = {}, s2[8][4] = {};
#pragma unroll
        for (int kf = 0; kf < 8; kf++) {
            unsigned a0, a1, a2, a3, c0, c1, c2, c3;
            ldsm_x4(aQ1 + kf * 32, a0, a1, a2, a3);
            ldsm_x4(aQ2 + kf * 32, c0, c1, c2, c3);
#pragma unroll
            for (int nq = 0; nq < 4; nq++) {
                unsigned b0, b1, b2, b3;
                ldsm_x4(bK1c + nq * 16 * LQ * 4 + kf * 32, b0, b1, b2, b3);
                mma_tf32(s1[2*nq],   a0, a1, a2, a3, b0, b1);
                mma_tf32(s1[2*nq+1], a0, a1, a2, a3, b2, b3);
                ldsm_x4(bK2c + nq * 16 * LQ * 4 + kf * 32, b0, b1, b2, b3);
                mma_tf32(s2[2*nq],   c0, c1, c2, c3, b0, b1);
                mma_tf32(s2[2*nq+1], c0, c1, c2, c3, b2, b3);
            }
        }

        // ---- online softmax, branch 1 then branch 2 ----
#pragma unroll
        for (int br = 0; br < 2; br++) {
            float (&s)[8][4] = br ? s2 : s1;
            float (&m)[2] = br ? m2 : m1;
            float (&l)[2] = br ? l2 : l1;
            float (&O)[16][4] = br ? O2 : O1;

            float mx0 = -1e30f, mx1 = -1e30f;
#pragma unroll
            for (int nf = 0; nf < 8; nf++) {
                mx0 = fmaxf(mx0, fmaxf(s[nf][0], s[nf][1]));
                mx1 = fmaxf(mx1, fmaxf(s[nf][2], s[nf][3]));
            }
#pragma unroll
            for (int off = 1; off < 4; off <<= 1) {
                mx0 = fmaxf(mx0, __shfl_xor_sync(0xffffffffu, mx0, off));
                mx1 = fmaxf(mx1, __shfl_xor_sync(0xffffffffu, mx1, off));
            }
            float mn0 = fmaxf(m[0], mx0), mn1 = fmaxf(m[1], mx1);
            float sc0 = __expf(m[0] - mn0), sc1 = __expf(m[1] - mn1);
            m[0] = mn0; m[1] = mn1;

            float rs0 = 0.f, rs1 = 0.f;
#pragma unroll
            for (int nf = 0; nf < 8; nf++) {
                s[nf][0] = __expf(s[nf][0] - mn0);
                s[nf][1] = __expf(s[nf][1] - mn0);
                s[nf][2] = __expf(s[nf][2] - mn1);
                s[nf][3] = __expf(s[nf][3] - mn1);
                rs0 += s[nf][0] + s[nf][1];
                rs1 += s[nf][2] + s[nf][3];
            }
#pragma unroll
            for (int off = 1; off < 4; off <<= 1) {
                rs0 += __shfl_xor_sync(0xffffffffu, rs0, off);
                rs1 += __shfl_xor_sync(0xffffffffu, rs1, off);
            }
            l[0] = l[0] * sc0 + rs0;
            l[1] = l[1] * sc1 + rs1;
#pragma unroll
            for (int nf = 0; nf < 16; nf++) {
                O[nf][0] *= sc0; O[nf][1] *= sc0;
                O[nf][2] *= sc1; O[nf][3] *= sc1;
            }
        }

        // ---- P @ V, shared V fragments ----
#pragma unroll
        for (int kf = 0; kf < 8; kf++) {
            unsigned pa0, pa1, pa2, pa3, pb0, pb1, pb2, pb3;
            p_frag(s1[kf], lane, pa0, pa1, pa2, pa3);
            p_frag(s2[kf], lane, pb0, pb1, pb2, pb3);
#pragma unroll
            for (int nq = 0; nq < 8; nq++) {
                unsigned v0, v1, v2, v3;
                ldsm_x4(bVc + nq * 16 * LQ * 4 + kf * 32, v0, v1, v2, v3);
                mma_tf32(O1[2*nq],   pa0, pa1, pa2, pa3, v0, v1);
                mma_tf32(O1[2*nq+1], pa0, pa1, pa2, pa3, v2, v3);
                mma_tf32(O2[2*nq],   pb0, pb1, pb2, pb3, v0, v1);
                mma_tf32(O2[2*nq+1], pb0, pb1, pb2, pb3, v2, v3);
            }
        }

        __syncthreads();
        if (kt + 2 < NT) {
            int k0 = (kt + 2) * FSN;
            load_stage(st[cur], k1b + (size_t)k0 * DR, k2b + (size_t)k0 * DR,
                       vg + k0, tid);
        }
        CP_COMMIT();
    }

    // ---- epilogue: combine, transpose via smem, add x, write out ----
    __syncthreads();
    float* Os = sm;
    const float s2h = s2v[h];
    const int g = lane >> 2, tig = lane & 3;
    const int r0 = wid * 16 + g;
    const float i10 = 1.f / l1[0], i11 = 1.f / l1[1];
    const float i20 = s2h / l2[0], i21 = s2h / l2[1];
#pragma unroll
    for (int nf = 0; nf < 16; nf++) {
        int col = nf * 8 + tig * 2;
        Os[col * OSL + r0]           = O1[nf][0] * i10 - O2[nf][0] * i20;
        Os[(col + 1) * OSL + r0]     = O1[nf][1] * i10 - O2[nf][1] * i20;
        Os[col * OSL + r0 + 8]       = O1[nf][2] * i11 - O2[nf][2] * i21;
        Os[(col + 1) * OSL + r0 + 8] = O1[nf][3] * i11 - O2[nf][3] * i21;
    }
    __syncthreads();
#pragma unroll
    for (int i = 0; i < 16; i++) {
        int idx = tid + i * 256;
        int qv = idx & 31, n = idx >> 5;
        size_t o = ((size_t)(b * F_ + h * HF + n)) * T_ + q0 + qv * 4;
        float4 xv = *(const float4*)&x[o];
        float4 r  = *(const float4*)&Os[n * OSL + qv * 4];
        float4 ov = { xv.x + r.x, xv.y + r.y, xv.z + r.z, xv.w + r.w };
        *(float4*)&out[o] = ov;
    }
}

#define FLASH_SMEM (768 * LQ * 4)   // Q1+Q2 (256*LQ) + 2 stages (256*LQ each)

// ---------------------------------------------------------------------------
extern "C" void kernel_launch(void* const* d_in, const int* in_sizes, int n_in,
                              void* d_out, int out_size)
{
    const float* x  = (const float*)d_in[0];
    const float* Wq = (const float*)d_in[1];
    const float* bq = (const float*)d_in[2];
    const float* Wk = (const float*)d_in[3];
    const float* bk = (const float*)d_in[4];
    const float* Wv = (const float*)d_in[5];
    const float* bv = (const float*)d_in[6];
    const float* s2 = (const float*)d_in[7];
    float* out = (float*)d_out;

    cudaFuncSetAttribute(flash_kernel,
                         cudaFuncAttributeMaxDynamicSharedMemorySize, FLASH_SMEM);

    qkv_fused<<<dim3(T_ / BM, F_ / BN, 3 * B_), 256>>>(x, Wq, bq, Wk, bk, Wv, bv);

    flash_kernel<<<dim3(T_ / 128, B_ * H_), 256, FLASH_SMEM>>>(x, s2, out);
}